// round 2
// baseline (speedup 1.0000x reference)
#include <cuda_runtime.h>

#define NQ 4
#define BATCH 128
#define PATCHES 196          // 14*14
#define LTOT (BATCH*PATCHES) // 25088
#define FEAT 784
#define H1 64
#define NOUT 10

__device__ float g_feat[BATCH * FEAT];

// ---------------------------------------------------------------------------
// Kernel 1: full 4-qubit circuit per patch, state in registers.
// Amp index: idx = q0*8 + q1*4 + q2*2 + q3  (qubit q <-> bit (3-q))
// ---------------------------------------------------------------------------
__global__ void __launch_bounds__(256) circuit_kernel(
    const float* __restrict__ x, const float* __restrict__ w)
{
    __shared__ float cw[60];
    __shared__ float sw[60];
    int tid = threadIdx.x;
    if (tid < 60) {
        float hv = 0.5f * w[tid];
        float s, c;
        sincosf(hv, &s, &c);
        cw[tid] = c;
        sw[tid] = s;
    }
    __syncthreads();

    int p = blockIdx.x * blockDim.x + tid;
    if (p >= LTOT) return;

    int b  = p / PATCHES;
    int pp = p % PATCHES;
    int i  = pp / 14;
    int j  = pp % 14;

    const float* xb = x + b * 784;
    const float TWO_PI = 6.2831853071795864769f;
    float ang0 = TWO_PI * xb[(2*i)  *28 + 2*j    ];
    float ang1 = TWO_PI * xb[(2*i)  *28 + 2*j + 1];
    float ang2 = TWO_PI * xb[(2*i+1)*28 + 2*j    ];
    float ang3 = TWO_PI * xb[(2*i+1)*28 + 2*j + 1];

    float sr[16], si[16];
#pragma unroll
    for (int k = 0; k < 16; k++) { sr[k] = 0.0f; si[k] = 0.0f; }
    sr[0] = 1.0f;

    // ---- Rx encoding, per-patch angles ----
    float angs[4] = {ang0, ang1, ang2, ang3};
#pragma unroll
    for (int q = 0; q < 4; q++) {
        float s, c;
        sincosf(0.5f * angs[q], &s, &c);
        int st = 1 << (3 - q);
#pragma unroll
        for (int k = 0; k < 16; k++) {
            if (k & st) continue;
            int k1 = k | st;
            float ar = sr[k],  ai = si[k];
            float br = sr[k1], bi = si[k1];
            // gate [[c, -i s],[-i s, c]]
            sr[k]  = c*ar + s*bi;
            si[k]  = c*ai - s*br;
            sr[k1] = c*br + s*ai;
            si[k1] = c*bi - s*ar;
        }
    }

    // ---- 5 layers: Ry(all q), Rz(all q), Ry(all q); ring CNOTs for layer<4 ----
#pragma unroll 1
    for (int layer = 0; layer < 5; layer++) {
        int base = layer * 12;

        // Ry block (weights base..base+3)
#pragma unroll
        for (int q = 0; q < 4; q++) {
            float c = cw[base + q];
            float s = sw[base + q];
            int st = 1 << (3 - q);
#pragma unroll
            for (int k = 0; k < 16; k++) {
                if (k & st) continue;
                int k1 = k | st;
                float ar = sr[k],  ai = si[k];
                float br = sr[k1], bi = si[k1];
                sr[k]  = c*ar - s*br;
                si[k]  = c*ai - s*bi;
                sr[k1] = s*ar + c*br;
                si[k1] = s*ai + c*bi;
            }
        }
        // Rz block (weights base+4..base+7): diag(e^{-it/2}, e^{+it/2})
#pragma unroll
        for (int q = 0; q < 4; q++) {
            float c = cw[base + 4 + q];
            float s = sw[base + 4 + q];
            int st = 1 << (3 - q);
#pragma unroll
            for (int k = 0; k < 16; k++) {
                float ar = sr[k], ai = si[k];
                if (k & st) { // * (c, +s)
                    sr[k] = ar*c - ai*s;
                    si[k] = ai*c + ar*s;
                } else {      // * (c, -s)
                    sr[k] = ar*c + ai*s;
                    si[k] = ai*c - ar*s;
                }
            }
        }
        // Ry block (weights base+8..base+11)
#pragma unroll
        for (int q = 0; q < 4; q++) {
            float c = cw[base + 8 + q];
            float s = sw[base + 8 + q];
            int st = 1 << (3 - q);
#pragma unroll
            for (int k = 0; k < 16; k++) {
                if (k & st) continue;
                int k1 = k | st;
                float ar = sr[k],  ai = si[k];
                float br = sr[k1], bi = si[k1];
                sr[k]  = c*ar - s*br;
                si[k]  = c*ai - s*bi;
                sr[k1] = s*ar + c*br;
                si[k1] = s*ai + c*bi;
            }
        }

        if (layer < 4) {
            // ring: CNOT(0,1), CNOT(1,2), CNOT(2,3), CNOT(3,0)
#pragma unroll
            for (int q = 0; q < 4; q++) {
                int cmask = 1 << (3 - q);
                int tmask = 1 << (3 - ((q + 1) & 3));
#pragma unroll
                for (int k = 0; k < 16; k++) {
                    if ((k & cmask) && !(k & tmask)) {
                        int k1 = k | tmask;
                        float tr = sr[k];  sr[k]  = sr[k1]; sr[k1] = tr;
                        float ti = si[k];  si[k]  = si[k1]; si[k1] = ti;
                    }
                }
            }
        }
    }

    // ---- <Z_q> expectations ----
    float prob[16];
#pragma unroll
    for (int k = 0; k < 16; k++) prob[k] = sr[k]*sr[k] + si[k]*si[k];

    float* f = g_feat + b * FEAT + pp * 4;
#pragma unroll
    for (int q = 0; q < 4; q++) {
        int mask = 1 << (3 - q);
        float e = 0.0f;
#pragma unroll
        for (int k = 0; k < 16; k++)
            e += (k & mask) ? -prob[k] : prob[k];
        f[q] = e;
    }
}

// ---------------------------------------------------------------------------
// Kernel 2: fused FC1 + ReLU + FC2. One block per batch row, 64 threads.
// ---------------------------------------------------------------------------
__global__ void __launch_bounds__(64) fc_kernel(
    const float* __restrict__ fc1_w, const float* __restrict__ fc1_b,
    const float* __restrict__ fc2_w, const float* __restrict__ fc2_b,
    float* __restrict__ out)
{
    __shared__ float feat_s[FEAT];
    __shared__ float h_s[H1];
    int b = blockIdx.x;
    int t = threadIdx.x;

    const float* fr = g_feat + b * FEAT;
    for (int f = t; f < FEAT; f += 64) feat_s[f] = fr[f];
    __syncthreads();

    float acc = fc1_b[t];
    const float4* wr = (const float4*)(fc1_w + t * FEAT);
    const float4* fs = (const float4*)feat_s;
#pragma unroll 8
    for (int f = 0; f < FEAT / 4; f++) {
        float4 wv = wr[f];
        float4 fv = fs[f];
        acc += wv.x * fv.x + wv.y * fv.y + wv.z * fv.z + wv.w * fv.w;
    }
    h_s[t] = fmaxf(acc, 0.0f);
    __syncthreads();

    if (t < NOUT) {
        float a = fc2_b[t];
        const float* w2 = fc2_w + t * H1;
#pragma unroll
        for (int o = 0; o < H1; o++) a += h_s[o] * w2[o];
        out[b * NOUT + t] = a;
    }
}

extern "C" void kernel_launch(void* const* d_in, const int* in_sizes, int n_in,
                              void* d_out, int out_size)
{
    const float* x     = (const float*)d_in[0];
    const float* w     = (const float*)d_in[1];
    const float* fc1_w = (const float*)d_in[2];
    const float* fc1_b = (const float*)d_in[3];
    const float* fc2_w = (const float*)d_in[4];
    const float* fc2_b = (const float*)d_in[5];
    float* out = (float*)d_out;

    circuit_kernel<<<(LTOT + 255) / 256, 256>>>(x, w);
    fc_kernel<<<BATCH, 64>>>(fc1_w, fc1_b, fc2_w, fc2_b, out);
}

// round 4
// speedup vs baseline: 1.5533x; 1.5533x over previous
#include <cuda_runtime.h>

#define NQ 4
#define BATCH 128
#define PATCHES 196          // 14*14
#define LTOT (BATCH*PATCHES) // 25088
#define FEAT 784
#define H1 64
#define NOUT 10

__device__ float g_feat[BATCH * FEAT];

// ---------------------------------------------------------------------------
// Kernel 1: full 4-qubit circuit per patch, state in registers.
// Amp index: idx = q0*8 + q1*4 + q2*2 + q3  (qubit q <-> bit (3-q))
// ---------------------------------------------------------------------------
__global__ void __launch_bounds__(256) circuit_kernel(
    const float* __restrict__ x, const float* __restrict__ w)
{
    __shared__ float cw[60];
    __shared__ float sw[60];
    int tid = threadIdx.x;
    if (tid < 60) {
        float hv = 0.5f * w[tid];
        float s, c;
        sincosf(hv, &s, &c);
        cw[tid] = c;
        sw[tid] = s;
    }
    __syncthreads();

    int p = blockIdx.x * blockDim.x + tid;
    if (p >= LTOT) return;

    int b  = p / PATCHES;
    int pp = p % PATCHES;
    int i  = pp / 14;
    int j  = pp % 14;

    const float* xb = x + b * 784;
    const float TWO_PI = 6.2831853071795864769f;
    float ang0 = TWO_PI * xb[(2*i)  *28 + 2*j    ];
    float ang1 = TWO_PI * xb[(2*i)  *28 + 2*j + 1];
    float ang2 = TWO_PI * xb[(2*i+1)*28 + 2*j    ];
    float ang3 = TWO_PI * xb[(2*i+1)*28 + 2*j + 1];

    float sr[16], si[16];
#pragma unroll
    for (int k = 0; k < 16; k++) { sr[k] = 0.0f; si[k] = 0.0f; }
    sr[0] = 1.0f;

    // ---- Rx encoding, per-patch angles ----
    float angs[4] = {ang0, ang1, ang2, ang3};
#pragma unroll
    for (int q = 0; q < 4; q++) {
        float s, c;
        sincosf(0.5f * angs[q], &s, &c);
        int st = 1 << (3 - q);
#pragma unroll
        for (int k = 0; k < 16; k++) {
            if (k & st) continue;
            int k1 = k | st;
            float ar = sr[k],  ai = si[k];
            float br = sr[k1], bi = si[k1];
            // gate [[c, -i s],[-i s, c]]
            sr[k]  = c*ar + s*bi;
            si[k]  = c*ai - s*br;
            sr[k1] = c*br + s*ai;
            si[k1] = c*bi - s*ar;
        }
    }

    // ---- 5 layers: Ry(all q), Rz(all q), Ry(all q); ring CNOTs for layer<4 ----
#pragma unroll
    for (int layer = 0; layer < 5; layer++) {
        int base = layer * 12;

        // Ry block (weights base..base+3)
#pragma unroll
        for (int q = 0; q < 4; q++) {
            float c = cw[base + q];
            float s = sw[base + q];
            int st = 1 << (3 - q);
#pragma unroll
            for (int k = 0; k < 16; k++) {
                if (k & st) continue;
                int k1 = k | st;
                float ar = sr[k],  ai = si[k];
                float br = sr[k1], bi = si[k1];
                sr[k]  = c*ar - s*br;
                si[k]  = c*ai - s*bi;
                sr[k1] = s*ar + c*br;
                si[k1] = s*ai + c*bi;
            }
        }
        // Rz block (weights base+4..base+7): diag(e^{-it/2}, e^{+it/2})
#pragma unroll
        for (int q = 0; q < 4; q++) {
            float c = cw[base + 4 + q];
            float s = sw[base + 4 + q];
            int st = 1 << (3 - q);
#pragma unroll
            for (int k = 0; k < 16; k++) {
                float ar = sr[k], ai = si[k];
                if (k & st) { // * (c, +s)
                    sr[k] = ar*c - ai*s;
                    si[k] = ai*c + ar*s;
                } else {      // * (c, -s)
                    sr[k] = ar*c + ai*s;
                    si[k] = ai*c - ar*s;
                }
            }
        }
        // Ry block (weights base+8..base+11)
#pragma unroll
        for (int q = 0; q < 4; q++) {
            float c = cw[base + 8 + q];
            float s = sw[base + 8 + q];
            int st = 1 << (3 - q);
#pragma unroll
            for (int k = 0; k < 16; k++) {
                if (k & st) continue;
                int k1 = k | st;
                float ar = sr[k],  ai = si[k];
                float br = sr[k1], bi = si[k1];
                sr[k]  = c*ar - s*br;
                si[k]  = c*ai - s*bi;
                sr[k1] = s*ar + c*br;
                si[k1] = s*ai + c*bi;
            }
        }

        if (layer < 4) {
            // ring: CNOT(0,1), CNOT(1,2), CNOT(2,3), CNOT(3,0)
#pragma unroll
            for (int q = 0; q < 4; q++) {
                int cmask = 1 << (3 - q);
                int tmask = 1 << (3 - ((q + 1) & 3));
#pragma unroll
                for (int k = 0; k < 16; k++) {
                    if ((k & cmask) && !(k & tmask)) {
                        int k1 = k | tmask;
                        float tr = sr[k];  sr[k]  = sr[k1]; sr[k1] = tr;
                        float ti = si[k];  si[k]  = si[k1]; si[k1] = ti;
                    }
                }
            }
        }
    }

    // ---- <Z_q> expectations ----
    float prob[16];
#pragma unroll
    for (int k = 0; k < 16; k++) prob[k] = sr[k]*sr[k] + si[k]*si[k];

    float* f = g_feat + b * FEAT + pp * 4;
#pragma unroll
    for (int q = 0; q < 4; q++) {
        int mask = 1 << (3 - q);
        float e = 0.0f;
#pragma unroll
        for (int k = 0; k < 16; k++)
            e += (k & mask) ? -prob[k] : prob[k];
        f[q] = e;
    }
}

// ---------------------------------------------------------------------------
// Kernel 2: fused FC1 + ReLU + FC2. One block per batch row, 256 threads.
// 4 threads cooperate per FC1 neuron (split-K over 784), shfl-reduce.
// ---------------------------------------------------------------------------
__global__ void __launch_bounds__(256) fc_kernel(
    const float* __restrict__ fc1_w, const float* __restrict__ fc1_b,
    const float* __restrict__ fc2_w, const float* __restrict__ fc2_b,
    float* __restrict__ out)
{
    __shared__ float feat_s[FEAT];
    __shared__ float h_s[H1];
    int b = blockIdx.x;
    int t = threadIdx.x;

    // load feature row into smem as float4s
    const float4* fr4 = (const float4*)(g_feat + b * FEAT);
    float4* fs4 = (float4*)feat_s;
    if (t < FEAT / 4) fs4[t] = fr4[t];   // 196 float4 loads
    __syncthreads();

    // FC1: neuron = t/4, each of 4 parts handles 49 contiguous float4
    int neuron = t >> 2;
    int part   = t & 3;
    const float4* wr = (const float4*)(fc1_w + neuron * FEAT) + part * 49;
    const float4* fv = fs4 + part * 49;
    float acc = 0.0f;
#pragma unroll
    for (int f = 0; f < 49; f++) {
        float4 wv = wr[f];
        float4 xv = fv[f];
        acc += wv.x * xv.x + wv.y * xv.y + wv.z * xv.z + wv.w * xv.w;
    }
    // reduce across the 4 parts (lanes part..part^1 within width-4 groups)
    acc += __shfl_down_sync(0xffffffffu, acc, 2, 4);
    acc += __shfl_down_sync(0xffffffffu, acc, 1, 4);
    if (part == 0) h_s[neuron] = fmaxf(acc + fc1_b[neuron], 0.0f);
    __syncthreads();

    // FC2: 10 outputs, one thread each (64 smem loads, fully unrolled)
    if (t < NOUT) {
        float a = fc2_b[t];
        const float* w2 = fc2_w + t * H1;
#pragma unroll
        for (int o = 0; o < H1; o++) a += h_s[o] * w2[o];
        out[b * NOUT + t] = a;
    }
}

extern "C" void kernel_launch(void* const* d_in, const int* in_sizes, int n_in,
                              void* d_out, int out_size)
{
    const float* x     = (const float*)d_in[0];
    const float* w     = (const float*)d_in[1];
    const float* fc1_w = (const float*)d_in[2];
    const float* fc1_b = (const float*)d_in[3];
    const float* fc2_w = (const float*)d_in[4];
    const float* fc2_b = (const float*)d_in[5];
    float* out = (float*)d_out;

    circuit_kernel<<<(LTOT + 255) / 256, 256>>>(x, w);
    fc_kernel<<<BATCH, 256>>>(fc1_w, fc1_b, fc2_w, fc2_b, out);
}

// round 5
// speedup vs baseline: 1.8621x; 1.1988x over previous
#include <cuda_runtime.h>

#define NQ 4
#define BATCH 128
#define PATCHES 196          // 14*14
#define LTOT (BATCH*PATCHES) // 25088
#define FEAT 784
#define H1 64
#define NOUT 10

__device__ float g_feat[BATCH * FEAT];

// ---------------------------------------------------------------------------
// Kernel 1: full 4-qubit circuit per patch, state in registers.
// Amp index: idx = q0*8 + q1*4 + q2*2 + q3  (qubit q <-> bit (3-q))
// ---------------------------------------------------------------------------
__global__ void __launch_bounds__(256) circuit_kernel(
    const float* __restrict__ x, const float* __restrict__ w)
{
    __shared__ float cw[60];
    __shared__ float sw[60];
    int tid = threadIdx.x;
    if (tid < 60) {
        float hv = 0.5f * w[tid];
        float s, c;
        sincosf(hv, &s, &c);
        cw[tid] = c;
        sw[tid] = s;
    }
    __syncthreads();

    int p = blockIdx.x * blockDim.x + tid;
    if (p >= LTOT) return;

    int b  = p / PATCHES;
    int pp = p % PATCHES;
    int i  = pp / 14;
    int j  = pp % 14;

    const float* xb = x + b * 784;
    const float TWO_PI = 6.2831853071795864769f;
    float ang0 = TWO_PI * xb[(2*i)  *28 + 2*j    ];
    float ang1 = TWO_PI * xb[(2*i)  *28 + 2*j + 1];
    float ang2 = TWO_PI * xb[(2*i+1)*28 + 2*j    ];
    float ang3 = TWO_PI * xb[(2*i+1)*28 + 2*j + 1];

    float sr[16], si[16];
#pragma unroll
    for (int k = 0; k < 16; k++) { sr[k] = 0.0f; si[k] = 0.0f; }
    sr[0] = 1.0f;

    // ---- Rx encoding, per-patch angles ----
    float angs[4] = {ang0, ang1, ang2, ang3};
#pragma unroll
    for (int q = 0; q < 4; q++) {
        float s, c;
        sincosf(0.5f * angs[q], &s, &c);
        int st = 1 << (3 - q);
#pragma unroll
        for (int k = 0; k < 16; k++) {
            if (k & st) continue;
            int k1 = k | st;
            float ar = sr[k],  ai = si[k];
            float br = sr[k1], bi = si[k1];
            // gate [[c, -i s],[-i s, c]]
            sr[k]  = c*ar + s*bi;
            si[k]  = c*ai - s*br;
            sr[k1] = c*br + s*ai;
            si[k1] = c*bi - s*ar;
        }
    }

    // ---- 5 layers: Ry(all q), Rz(all q), Ry(all q); ring CNOTs for layer<4 ----
#pragma unroll
    for (int layer = 0; layer < 5; layer++) {
        int base = layer * 12;

        // Ry block (weights base..base+3)
#pragma unroll
        for (int q = 0; q < 4; q++) {
            float c = cw[base + q];
            float s = sw[base + q];
            int st = 1 << (3 - q);
#pragma unroll
            for (int k = 0; k < 16; k++) {
                if (k & st) continue;
                int k1 = k | st;
                float ar = sr[k],  ai = si[k];
                float br = sr[k1], bi = si[k1];
                sr[k]  = c*ar - s*br;
                si[k]  = c*ai - s*bi;
                sr[k1] = s*ar + c*br;
                si[k1] = s*ai + c*bi;
            }
        }
        // Rz block (weights base+4..base+7): diag(e^{-it/2}, e^{+it/2})
#pragma unroll
        for (int q = 0; q < 4; q++) {
            float c = cw[base + 4 + q];
            float s = sw[base + 4 + q];
            int st = 1 << (3 - q);
#pragma unroll
            for (int k = 0; k < 16; k++) {
                float ar = sr[k], ai = si[k];
                if (k & st) { // * (c, +s)
                    sr[k] = ar*c - ai*s;
                    si[k] = ai*c + ar*s;
                } else {      // * (c, -s)
                    sr[k] = ar*c + ai*s;
                    si[k] = ai*c - ar*s;
                }
            }
        }
        // Ry block (weights base+8..base+11)
#pragma unroll
        for (int q = 0; q < 4; q++) {
            float c = cw[base + 8 + q];
            float s = sw[base + 8 + q];
            int st = 1 << (3 - q);
#pragma unroll
            for (int k = 0; k < 16; k++) {
                if (k & st) continue;
                int k1 = k | st;
                float ar = sr[k],  ai = si[k];
                float br = sr[k1], bi = si[k1];
                sr[k]  = c*ar - s*br;
                si[k]  = c*ai - s*bi;
                sr[k1] = s*ar + c*br;
                si[k1] = s*ai + c*bi;
            }
        }

        if (layer < 4) {
            // ring: CNOT(0,1), CNOT(1,2), CNOT(2,3), CNOT(3,0)
#pragma unroll
            for (int q = 0; q < 4; q++) {
                int cmask = 1 << (3 - q);
                int tmask = 1 << (3 - ((q + 1) & 3));
#pragma unroll
                for (int k = 0; k < 16; k++) {
                    if ((k & cmask) && !(k & tmask)) {
                        int k1 = k | tmask;
                        float tr = sr[k];  sr[k]  = sr[k1]; sr[k1] = tr;
                        float ti = si[k];  si[k]  = si[k1]; si[k1] = ti;
                    }
                }
            }
        }
    }

    // ---- <Z_q> expectations ----
    float prob[16];
#pragma unroll
    for (int k = 0; k < 16; k++) prob[k] = sr[k]*sr[k] + si[k]*si[k];

    float* f = g_feat + b * FEAT + pp * 4;
#pragma unroll
    for (int q = 0; q < 4; q++) {
        int mask = 1 << (3 - q);
        float e = 0.0f;
#pragma unroll
        for (int k = 0; k < 16; k++)
            e += (k & mask) ? -prob[k] : prob[k];
        f[q] = e;
    }
}

// ---------------------------------------------------------------------------
// Kernel 2: fused FC1 + ReLU + FC2. One block per batch row, 1024 threads.
// 16 threads cooperate per FC1 neuron (strided split-K over 196 float4),
// shfl-reduce width 16. FC2 done warp-cooperatively (10 outputs x 32 lanes).
// ---------------------------------------------------------------------------
__global__ void __launch_bounds__(1024) fc_kernel(
    const float* __restrict__ fc1_w, const float* __restrict__ fc1_b,
    const float* __restrict__ fc2_w, const float* __restrict__ fc2_b,
    float* __restrict__ out)
{
    __shared__ float feat_s[FEAT];
    __shared__ float h_s[H1];
    int b = blockIdx.x;
    int t = threadIdx.x;

    // load feature row into smem as float4s (196 loads)
    const float4* fr4 = (const float4*)(g_feat + b * FEAT);
    float4* fs4 = (float4*)feat_s;
    if (t < FEAT / 4) fs4[t] = fr4[t];
    __syncthreads();

    // FC1: neuron = t/16, part = t%16; part handles float4 idx part, part+16, ...
    // (consecutive 16 lanes -> consecutive float4s: coalesced 256B segments)
    int neuron = t >> 4;
    int part   = t & 15;
    const float4* wr = (const float4*)(fc1_w + neuron * FEAT);
    float acc = 0.0f;
#pragma unroll
    for (int f = part; f < FEAT / 4; f += 16) {
        float4 wv = wr[f];
        float4 xv = fs4[f];
        acc += wv.x * xv.x + wv.y * xv.y + wv.z * xv.z + wv.w * xv.w;
    }
    // reduce across the 16 parts
    acc += __shfl_down_sync(0xffffffffu, acc, 8, 16);
    acc += __shfl_down_sync(0xffffffffu, acc, 4, 16);
    acc += __shfl_down_sync(0xffffffffu, acc, 2, 16);
    acc += __shfl_down_sync(0xffffffffu, acc, 1, 16);
    if (part == 0) h_s[neuron] = fmaxf(acc + fc1_b[neuron], 0.0f);
    __syncthreads();

    // FC2: 10 outputs, one warp each. Lane handles h indices 2*lane, 2*lane+1.
    if (t < NOUT * 32) {
        int o    = t >> 5;
        int lane = t & 31;
        const float* w2 = fc2_w + o * H1;
        float a = h_s[2*lane] * w2[2*lane] + h_s[2*lane + 1] * w2[2*lane + 1];
#pragma unroll
        for (int off = 16; off > 0; off >>= 1)
            a += __shfl_down_sync(0xffffffffu, a, off);
        if (lane == 0) out[b * NOUT + o] = a + fc2_b[o];
    }
}

extern "C" void kernel_launch(void* const* d_in, const int* in_sizes, int n_in,
                              void* d_out, int out_size)
{
    const float* x     = (const float*)d_in[0];
    const float* w     = (const float*)d_in[1];
    const float* fc1_w = (const float*)d_in[2];
    const float* fc1_b = (const float*)d_in[3];
    const float* fc2_w = (const float*)d_in[4];
    const float* fc2_b = (const float*)d_in[5];
    float* out = (float*)d_out;

    circuit_kernel<<<(LTOT + 255) / 256, 256>>>(x, w);
    fc_kernel<<<BATCH, 1024>>>(fc1_w, fc1_b, fc2_w, fc2_b, out);
}

// round 6
// speedup vs baseline: 1.8889x; 1.0144x over previous
#include <cuda_runtime.h>

#define NQ 4
#define BATCH 128
#define PATCHES 196          // 14*14
#define FEAT 784
#define H1 64
#define NOUT 10

// ---------------------------------------------------------------------------
// One fused kernel: block b handles batch row b.
//   Phase 1: threads 0..195 run the 4-qubit circuit for patch t, write the 4
//            <Z_q> features straight into smem feat_s[784].
//   Phase 2: all 512 threads do FC1 (8 threads per neuron, split-K) + ReLU,
//            then 10 warps do FC2.
// ---------------------------------------------------------------------------
__global__ void __launch_bounds__(512) fused_kernel(
    const float* __restrict__ x, const float* __restrict__ w,
    const float* __restrict__ fc1_w, const float* __restrict__ fc1_b,
    const float* __restrict__ fc2_w, const float* __restrict__ fc2_b,
    float* __restrict__ out)
{
    __shared__ float cw[60];
    __shared__ float sw[60];
    __shared__ float feat_s[FEAT];
    __shared__ float h_s[H1];

    int b = blockIdx.x;
    int t = threadIdx.x;

    if (t < 60) {
        float s, c;
        sincosf(0.5f * w[t], &s, &c);
        cw[t] = c;
        sw[t] = s;
    }
    __syncthreads();

    // ---------------- Phase 1: circuit, one patch per thread ----------------
    if (t < PATCHES) {
        int i = t / 14;
        int j = t % 14;
        const float* xb = x + b * FEAT;
        const float PI_F = 3.14159265358979323846f;  // 2*pi*x / 2
        float angs[4];
        angs[0] = PI_F * xb[(2*i)  *28 + 2*j    ];
        angs[1] = PI_F * xb[(2*i)  *28 + 2*j + 1];
        angs[2] = PI_F * xb[(2*i+1)*28 + 2*j    ];
        angs[3] = PI_F * xb[(2*i+1)*28 + 2*j + 1];

        float sr[16], si[16];
#pragma unroll
        for (int k = 0; k < 16; k++) { sr[k] = 0.0f; si[k] = 0.0f; }
        sr[0] = 1.0f;

        // Rx encoding (angles already halved above)
#pragma unroll
        for (int q = 0; q < 4; q++) {
            float s, c;
            __sincosf(angs[q], &s, &c);
            int st = 1 << (3 - q);
#pragma unroll
            for (int k = 0; k < 16; k++) {
                if (k & st) continue;
                int k1 = k | st;
                float ar = sr[k],  ai = si[k];
                float br = sr[k1], bi = si[k1];
                sr[k]  = c*ar + s*bi;
                si[k]  = c*ai - s*br;
                sr[k1] = c*br + s*ai;
                si[k1] = c*bi - s*ar;
            }
        }

        // 5 layers of Ry/Rz/Ry + ring CNOTs
#pragma unroll
        for (int layer = 0; layer < 5; layer++) {
            int base = layer * 12;
#pragma unroll
            for (int q = 0; q < 4; q++) {       // Ry
                float c = cw[base + q], s = sw[base + q];
                int st = 1 << (3 - q);
#pragma unroll
                for (int k = 0; k < 16; k++) {
                    if (k & st) continue;
                    int k1 = k | st;
                    float ar = sr[k],  ai = si[k];
                    float br = sr[k1], bi = si[k1];
                    sr[k]  = c*ar - s*br;
                    si[k]  = c*ai - s*bi;
                    sr[k1] = s*ar + c*br;
                    si[k1] = s*ai + c*bi;
                }
            }
#pragma unroll
            for (int q = 0; q < 4; q++) {       // Rz
                float c = cw[base + 4 + q], s = sw[base + 4 + q];
                int st = 1 << (3 - q);
#pragma unroll
                for (int k = 0; k < 16; k++) {
                    float ar = sr[k], ai = si[k];
                    if (k & st) {
                        sr[k] = ar*c - ai*s;
                        si[k] = ai*c + ar*s;
                    } else {
                        sr[k] = ar*c + ai*s;
                        si[k] = ai*c - ar*s;
                    }
                }
            }
#pragma unroll
            for (int q = 0; q < 4; q++) {       // Ry
                float c = cw[base + 8 + q], s = sw[base + 8 + q];
                int st = 1 << (3 - q);
#pragma unroll
                for (int k = 0; k < 16; k++) {
                    if (k & st) continue;
                    int k1 = k | st;
                    float ar = sr[k],  ai = si[k];
                    float br = sr[k1], bi = si[k1];
                    sr[k]  = c*ar - s*br;
                    si[k]  = c*ai - s*bi;
                    sr[k1] = s*ar + c*br;
                    si[k1] = s*ai + c*bi;
                }
            }
            if (layer < 4) {                    // ring CNOTs (register swaps)
#pragma unroll
                for (int q = 0; q < 4; q++) {
                    int cmask = 1 << (3 - q);
                    int tmask = 1 << (3 - ((q + 1) & 3));
#pragma unroll
                    for (int k = 0; k < 16; k++) {
                        if ((k & cmask) && !(k & tmask)) {
                            int k1 = k | tmask;
                            float tr = sr[k]; sr[k] = sr[k1]; sr[k1] = tr;
                            float ti = si[k]; si[k] = si[k1]; si[k1] = ti;
                        }
                    }
                }
            }
        }

        // <Z_q> expectations -> smem
        float prob[16];
#pragma unroll
        for (int k = 0; k < 16; k++) prob[k] = sr[k]*sr[k] + si[k]*si[k];
#pragma unroll
        for (int q = 0; q < 4; q++) {
            int mask = 1 << (3 - q);
            float e = 0.0f;
#pragma unroll
            for (int k = 0; k < 16; k++)
                e += (k & mask) ? -prob[k] : prob[k];
            feat_s[t * 4 + q] = e;
        }
    }
    __syncthreads();

    // ---------------- Phase 2: FC1 (8 threads / neuron) + ReLU --------------
    {
        const float4* fs4 = (const float4*)feat_s;
        int neuron = t >> 3;        // 0..63
        int part   = t & 7;         // 0..7
        const float4* wr = (const float4*)(fc1_w + neuron * FEAT);
        float acc = 0.0f;
#pragma unroll
        for (int f = part; f < FEAT / 4; f += 8) {   // 24 or 25 iterations
            float4 wv = wr[f];
            float4 xv = fs4[f];
            acc += wv.x * xv.x + wv.y * xv.y + wv.z * xv.z + wv.w * xv.w;
        }
        acc += __shfl_down_sync(0xffffffffu, acc, 4, 8);
        acc += __shfl_down_sync(0xffffffffu, acc, 2, 8);
        acc += __shfl_down_sync(0xffffffffu, acc, 1, 8);
        if (part == 0) h_s[neuron] = fmaxf(acc + fc1_b[neuron], 0.0f);
    }
    __syncthreads();

    // ---------------- Phase 3: FC2, one warp per output ---------------------
    if (t < NOUT * 32) {
        int o    = t >> 5;
        int lane = t & 31;
        const float* w2 = fc2_w + o * H1;
        float a = h_s[2*lane] * w2[2*lane] + h_s[2*lane + 1] * w2[2*lane + 1];
#pragma unroll
        for (int off = 16; off > 0; off >>= 1)
            a += __shfl_down_sync(0xffffffffu, a, off);
        if (lane == 0) out[b * NOUT + o] = a + fc2_b[o];
    }
}

extern "C" void kernel_launch(void* const* d_in, const int* in_sizes, int n_in,
                              void* d_out, int out_size)
{
    const float* x     = (const float*)d_in[0];
    const float* w     = (const float*)d_in[1];
    const float* fc1_w = (const float*)d_in[2];
    const float* fc1_b = (const float*)d_in[3];
    const float* fc2_w = (const float*)d_in[4];
    const float* fc2_b = (const float*)d_in[5];
    float* out = (float*)d_out;

    fused_kernel<<<BATCH, 512>>>(x, w, fc1_w, fc1_b, fc2_w, fc2_b, out);
}